// round 14
// baseline (speedup 1.0000x reference)
#include <cuda_runtime.h>
#include <cuda_bf16.h>
#include <cstdint>
#include <math.h>

// Problem constants (fixed by the dataset)
#define BB 2
#define SS 2048
#define DD 512
#define HH 8
#define DH 64
#define BH (BB*HH)          // 16
#define MAXK 32
#define EPSF 1e-8f

// ---------------- scratch (static device globals; no allocs allowed) --------
__device__ float        g_q  [BB*HH*SS*DH];   // [B,H,S,64] fp32
__device__ float        g_kT [BB*HH*DH*SS];   // [B,H,64,S] fp32 (exact rescue)
__device__ __nv_bfloat16 g_kb[BB*HH*SS*DH];   // [B,H,S,64] bf16 (mma B operand)
__device__ float        g_v  [BB*HH*SS*DH];   // [B,H,S,64]
__device__ float        g_attn[BB*SS*DD];     // [B,S,D]

// ---------------- warp reduce helpers ---------------------------------------
__device__ __forceinline__ float warpMaxF(float v){
#pragma unroll
    for (int o = 16; o; o >>= 1) v = fmaxf(v, __shfl_xor_sync(0xffffffffu, v, o));
    return v;
}
__device__ __forceinline__ float warpSumF(float v){
#pragma unroll
    for (int o = 16; o; o >>= 1) v += __shfl_xor_sync(0xffffffffu, v, o);
    return v;
}
__device__ __forceinline__ unsigned warpMaxU(unsigned v){
#pragma unroll
    for (int o = 16; o; o >>= 1) { unsigned t = __shfl_xor_sync(0xffffffffu, v, o); v = t > v ? t : v; }
    return v;
}
__device__ __forceinline__ int warpSumI(int v){
#pragma unroll
    for (int o = 16; o; o >>= 1) v += __shfl_xor_sync(0xffffffffu, v, o);
    return v;
}
__device__ __forceinline__ unsigned ordf(float f){
    unsigned u = __float_as_uint(f);
    return (u & 0x80000000u) ? ~u : (u | 0x80000000u);
}
__device__ __forceinline__ float bf16lo(unsigned u){ return __uint_as_float(u << 16); }
__device__ __forceinline__ float bf16hi(unsigned u){ return __uint_as_float(u & 0xffff0000u); }

// bf16 mma m16n8k16: D = A(16x16,row) * B(16x8,col) + C, fp32 accum
__device__ __forceinline__ void mma16816(float c[4], const unsigned a[4],
                                         unsigned b0, unsigned b1){
    asm volatile(
        "mma.sync.aligned.m16n8k16.row.col.f32.bf16.bf16.f32 "
        "{%0,%1,%2,%3}, {%4,%5,%6,%7}, {%8,%9}, {%0,%1,%2,%3};"
        : "+f"(c[0]), "+f"(c[1]), "+f"(c[2]), "+f"(c[3])
        : "r"(a[0]), "r"(a[1]), "r"(a[2]), "r"(a[3]), "r"(b0), "r"(b1));
}

// ---------------- SGEMM: C[M,N] = A[M,K] * Bw[N,K]^T + bias ------------------
// BM=128 x BN=64 tiles, double-buffered, 3 CTAs/SM (R8-proven).
// MODE 0: plain store. MODE 1: q/kT/kb/v scatter.
template<int MODE>
__global__ __launch_bounds__(256, 3)
void sgemm_nt(const float* __restrict__ A, const float* __restrict__ Bw,
              const float* __restrict__ bias, float* __restrict__ C,
              int M, int N, int K)
{
    const int BM = 128, BN = 64, BK = 16;
    __shared__ float As[2][BK][BM + 4];
    __shared__ float Bs[2][BK][BN + 4];

    int tid = threadIdx.x;
    int tx = tid & 15, ty = tid >> 4;
    int bm = blockIdx.y * BM, bn = blockIdx.x * BN;

    int arow0 = tid >> 2, ac = (tid & 3) * 4;
    int arow1 = arow0 + 64;
    int brow  = tid >> 2, bc = ac;

    float acc[8][4];
#pragma unroll
    for (int i = 0; i < 8; i++)
#pragma unroll
        for (int j = 0; j < 4; j++) acc[i][j] = 0.f;

    const float* Ab = A + (size_t)bm * K;
    const float* Bb = Bw + (size_t)bn * K;

    float4 pa0, pa1, pb0;

    pa0 = *(const float4*)(Ab + (size_t)arow0 * K + ac);
    pa1 = *(const float4*)(Ab + (size_t)arow1 * K + ac);
    pb0 = *(const float4*)(Bb + (size_t)brow  * K + bc);
    As[0][ac+0][arow0]=pa0.x; As[0][ac+1][arow0]=pa0.y; As[0][ac+2][arow0]=pa0.z; As[0][ac+3][arow0]=pa0.w;
    As[0][ac+0][arow1]=pa1.x; As[0][ac+1][arow1]=pa1.y; As[0][ac+2][arow1]=pa1.z; As[0][ac+3][arow1]=pa1.w;
    Bs[0][bc+0][brow ]=pb0.x; Bs[0][bc+1][brow ]=pb0.y; Bs[0][bc+2][brow ]=pb0.z; Bs[0][bc+3][brow ]=pb0.w;
    __syncthreads();

    for (int k0 = 0; k0 < K; k0 += BK) {
        int buf = (k0 >> 4) & 1;
        bool more = (k0 + BK) < K;
        if (more) {
            int kn = k0 + BK;
            pa0 = *(const float4*)(Ab + (size_t)arow0 * K + kn + ac);
            pa1 = *(const float4*)(Ab + (size_t)arow1 * K + kn + ac);
            pb0 = *(const float4*)(Bb + (size_t)brow  * K + kn + bc);
        }
#pragma unroll
        for (int k = 0; k < BK; k++) {
            float4 a0 = *(const float4*)&As[buf][k][ty * 8];
            float4 a1 = *(const float4*)&As[buf][k][ty * 8 + 4];
            float4 b0 = *(const float4*)&Bs[buf][k][tx * 4];
            float av[8] = {a0.x,a0.y,a0.z,a0.w,a1.x,a1.y,a1.z,a1.w};
            float bv[4] = {b0.x,b0.y,b0.z,b0.w};
#pragma unroll
            for (int i = 0; i < 8; i++)
#pragma unroll
                for (int j = 0; j < 4; j++) acc[i][j] = fmaf(av[i], bv[j], acc[i][j]);
        }
        if (more) {
            int nb = buf ^ 1;
            As[nb][ac+0][arow0]=pa0.x; As[nb][ac+1][arow0]=pa0.y; As[nb][ac+2][arow0]=pa0.z; As[nb][ac+3][arow0]=pa0.w;
            As[nb][ac+0][arow1]=pa1.x; As[nb][ac+1][arow1]=pa1.y; As[nb][ac+2][arow1]=pa1.z; As[nb][ac+3][arow1]=pa1.w;
            Bs[nb][bc+0][brow ]=pb0.x; Bs[nb][bc+1][brow ]=pb0.y; Bs[nb][bc+2][brow ]=pb0.z; Bs[nb][bc+3][brow ]=pb0.w;
        }
        __syncthreads();
    }

    if (MODE == 0) {
#pragma unroll
        for (int i = 0; i < 8; i++) {
            int mrow = bm + ty * 8 + i;
            int col = bn + tx * 4;
            float4 bv = *(const float4*)(bias + col);
            float4 o;
            o.x = acc[i][0] + bv.x; o.y = acc[i][1] + bv.y;
            o.z = acc[i][2] + bv.z; o.w = acc[i][3] + bv.w;
            *(float4*)(C + (size_t)mrow * N + col) = o;
        }
    } else {
#pragma unroll
        for (int i = 0; i < 8; i++) {
            int mrow = bm + ty * 8 + i;
            int b = mrow >> 11;          // S = 2048
            int s = mrow & 2047;
#pragma unroll
            for (int j = 0; j < 4; j++) {
                int n = bn + tx * 4 + j;
                float val = acc[i][j] + bias[n];
                int sec = n >> 9;        // 0:q 1:k 2:v (D = 512)
                int nn  = n & 511;
                int head = nn >> 6, d = nn & 63;
                size_t sd = ((size_t)((b*HH+head)*SS) + s)*DH + d;
                if (sec == 0) {
                    g_q[sd] = val;
                } else if (sec == 1) {
                    g_kT[((size_t)((b*HH+head)*DH) + d)*SS + s] = val;
                    g_kb[sd] = __float2bfloat16(val);
                } else {
                    g_v[sd] = val;
                }
            }
        }
    }
}

// ---------------- small SGEMM for proj: 64x64 tiles (wave-packing fix) -------
__global__ __launch_bounds__(256, 4)
void sgemm64(const float* __restrict__ A, const float* __restrict__ Bw,
             const float* __restrict__ bias, float* __restrict__ C,
             int M, int N, int K)
{
    const int BT = 64, BK = 16;
    __shared__ float As[2][BK][BT + 4];
    __shared__ float Bs[2][BK][BT + 4];

    int tid = threadIdx.x;
    int tx = tid & 15, ty = tid >> 4;        // 16x16: 4 cols, 4 rows each
    int bm = blockIdx.y * BT, bn = blockIdx.x * BT;

    int lrow = tid >> 2, lc = (tid & 3) * 4; // 256 f4 per operand, 1/thread

    float acc[4][4];
#pragma unroll
    for (int i = 0; i < 4; i++)
#pragma unroll
        for (int j = 0; j < 4; j++) acc[i][j] = 0.f;

    const float* Ab = A + (size_t)bm * K;
    const float* Bb = Bw + (size_t)bn * K;

    float4 pa, pb;
    pa = *(const float4*)(Ab + (size_t)lrow * K + lc);
    pb = *(const float4*)(Bb + (size_t)lrow * K + lc);
    As[0][lc+0][lrow]=pa.x; As[0][lc+1][lrow]=pa.y; As[0][lc+2][lrow]=pa.z; As[0][lc+3][lrow]=pa.w;
    Bs[0][lc+0][lrow]=pb.x; Bs[0][lc+1][lrow]=pb.y; Bs[0][lc+2][lrow]=pb.z; Bs[0][lc+3][lrow]=pb.w;
    __syncthreads();

    for (int k0 = 0; k0 < K; k0 += BK) {
        int buf = (k0 >> 4) & 1;
        bool more = (k0 + BK) < K;
        if (more) {
            int kn = k0 + BK;
            pa = *(const float4*)(Ab + (size_t)lrow * K + kn + lc);
            pb = *(const float4*)(Bb + (size_t)lrow * K + kn + lc);
        }
#pragma unroll
        for (int k = 0; k < BK; k++) {
            float4 a0 = *(const float4*)&As[buf][k][ty * 4];
            float4 b0 = *(const float4*)&Bs[buf][k][tx * 4];
            float av[4] = {a0.x,a0.y,a0.z,a0.w};
            float bv[4] = {b0.x,b0.y,b0.z,b0.w};
#pragma unroll
            for (int i = 0; i < 4; i++)
#pragma unroll
                for (int j = 0; j < 4; j++) acc[i][j] = fmaf(av[i], bv[j], acc[i][j]);
        }
        if (more) {
            int nb = buf ^ 1;
            As[nb][lc+0][lrow]=pa.x; As[nb][lc+1][lrow]=pa.y; As[nb][lc+2][lrow]=pa.z; As[nb][lc+3][lrow]=pa.w;
            Bs[nb][lc+0][lrow]=pb.x; Bs[nb][lc+1][lrow]=pb.y; Bs[nb][lc+2][lrow]=pb.z; Bs[nb][lc+3][lrow]=pb.w;
        }
        __syncthreads();
    }

#pragma unroll
    for (int i = 0; i < 4; i++) {
        int mrow = bm + ty * 4 + i;
        int col = bn + tx * 4;
        float4 bv = *(const float4*)(bias + col);
        float4 o;
        o.x = acc[i][0] + bv.x; o.y = acc[i][1] + bv.y;
        o.z = acc[i][2] + bv.z; o.w = acc[i][3] + bv.w;
        *(float4*)(C + (size_t)mrow * N + col) = o;
    }
}

// ---------------- fused attention v8: TQ=32, 1024 threads --------------------
// 32 warps = (M-half, N-slot): warps 0-15 compute rows 0-15, warps 16-31 rows
// 16-31, with warp (mh, wn) doing the m16n8k16 mma for cols wn*8 of each
// staged 128-row K chunk (double-buffered pipeline, R13-proven). Each staged
// chunk now serves 32 score rows -> K L2 traffic halved. Phase 2 (warp w owns
// row w): identical to v7 (R11/R13-proven numerics).
#define TQ 32
#define ATHREADS 1024
#define CAP 64
#define MARGIN 0.05f
#define SROW 2056                        // bf16 per score row (2048 + 8 pad)
#define KROW 72                          // bf16 per staged K row (64 + 8 pad)

#define OFF_KB0 (TQ*SROW*2)              // 131584
#define OFF_KB1 (OFF_KB0 + 128*KROW*2)   // + 18432
#define OFF_QB  (OFF_KB1 + 128*KROW*2)   // + 18432
#define OFF_CNT (OFF_QB + TQ*DH*2)       // + 4096
#define OFF_IDX (OFF_CNT + 128)
#define OFF_EXV (OFF_IDX + TQ*CAP*2)
#define ATTN_SMEM (OFF_EXV + TQ*CAP*4)   // = 184960 bytes

__global__ __launch_bounds__(ATHREADS, 1)
void attn_kernel()
{
    extern __shared__ unsigned char smem[];
    unsigned short* s_sc = (unsigned short*)smem;             // [32][SROW]
    __nv_bfloat16* s_kb0 = (__nv_bfloat16*)(smem + OFF_KB0);  // [128][KROW]
    __nv_bfloat16* s_kb1 = (__nv_bfloat16*)(smem + OFF_KB1);  // [128][KROW]
    __nv_bfloat16* s_qb = (__nv_bfloat16*)(smem + OFF_QB);    // [32][64]
    int*   s_cnt = (int*)(smem + OFF_CNT);                    // [32]
    unsigned short* s_idx = (unsigned short*)(smem + OFF_IDX);// [32][CAP]
    float* s_exv = (float*)(smem + OFF_EXV);                  // [32][CAP]

    int bh = blockIdx.y;
    int q0 = blockIdx.x * TQ;
    const float* Q  = g_q  + ((size_t)bh * SS + q0) * DH;
    const float* KT = g_kT + (size_t)bh * DH * SS;
    const __nv_bfloat16* Kb = g_kb + (size_t)bh * SS * DH;
    const float* V  = g_v  + (size_t)bh * SS * DH;
    int tid = threadIdx.x;
    int lane = tid & 31, w = tid >> 5;

    // load Q tile bf16 copy (2048 elems, 2/thread)
    for (int e = tid; e < TQ * DH; e += ATHREADS)
        s_qb[e] = __float2bfloat16(Q[e]);
    if (tid < TQ) s_cnt[tid] = 0;
    __syncthreads();

    const float scale = 0.125f;   // 1/sqrt(64)
    int r4 = lane >> 2, cq = (lane & 3) * 2;
    int mh = w >> 4;              // M-half (rows mh*16 .. mh*16+15)
    int wn = w & 15;              // N-slot (cols wn*8 per chunk)
    int mrow = mh * 16;

    // A fragments (Q rows of this M-half), persistent across chunks
    unsigned afr[4][4];
#pragma unroll
    for (int kk = 0; kk < 4; kk++) {
        int cb = kk * 16 + cq;
        afr[kk][0] = *(const unsigned*)&s_qb[(mrow + r4    ) * DH + cb    ];
        afr[kk][1] = *(const unsigned*)&s_qb[(mrow + r4 + 8) * DH + cb    ];
        afr[kk][2] = *(const unsigned*)&s_qb[(mrow + r4    ) * DH + cb + 8];
        afr[kk][3] = *(const unsigned*)&s_qb[(mrow + r4 + 8) * DH + cb + 8];
    }

    // staging lane geometry (1 float4 per thread per 128-row chunk)
    int row0 = tid >> 3, c80 = tid & 7;

    // ---- phase 1: 16 chunks of 128 K-rows, double-buffered -----------------
    float4 rA, rB;
    rA = *(const float4*)(Kb + ((size_t)row0) * DH + c80 * 8);
    *(float4*)((char*)s_kb0 + row0 * (KROW*2) + c80 * 16) = rA;
    rB = *(const float4*)(Kb + ((size_t)(128 + row0)) * DH + c80 * 8);
    __syncthreads();

#pragma unroll
    for (int ch = 0; ch < 16; ch += 2) {
        if (ch + 2 < 16)
            rA = *(const float4*)(Kb + ((size_t)((ch+2)*128 + row0)) * DH + c80 * 8);
        {
            float c[4] = {0.f, 0.f, 0.f, 0.f};
            const __nv_bfloat16* kbp = s_kb0 + (wn * 8 + r4) * KROW + cq;
#pragma unroll
            for (int kk = 0; kk < 4; kk++) {
                unsigned b0 = *(const unsigned*)(kbp + kk * 16);
                unsigned b1 = *(const unsigned*)(kbp + kk * 16 + 8);
                mma16816(c, afr[kk], b0, b1);
            }
            int n0 = ch * 128 + wn * 8;
            __nv_bfloat162 lo = __floats2bfloat162_rn(c[0] * scale, c[1] * scale);
            __nv_bfloat162 hi = __floats2bfloat162_rn(c[2] * scale, c[3] * scale);
            *(__nv_bfloat162*)&s_sc[(mrow + r4    ) * SROW + n0 + cq] = lo;
            *(__nv_bfloat162*)&s_sc[(mrow + r4 + 8) * SROW + n0 + cq] = hi;
        }
        *(float4*)((char*)s_kb1 + row0 * (KROW*2) + c80 * 16) = rB;
        __syncthreads();

        if (ch + 3 < 16)
            rB = *(const float4*)(Kb + ((size_t)((ch+3)*128 + row0)) * DH + c80 * 8);
        {
            float c[4] = {0.f, 0.f, 0.f, 0.f};
            const __nv_bfloat16* kbp = s_kb1 + (wn * 8 + r4) * KROW + cq;
#pragma unroll
            for (int kk = 0; kk < 4; kk++) {
                unsigned b0 = *(const unsigned*)(kbp + kk * 16);
                unsigned b1 = *(const unsigned*)(kbp + kk * 16 + 8);
                mma16816(c, afr[kk], b0, b1);
            }
            int n0 = (ch + 1) * 128 + wn * 8;
            __nv_bfloat162 lo = __floats2bfloat162_rn(c[0] * scale, c[1] * scale);
            __nv_bfloat162 hi = __floats2bfloat162_rn(c[2] * scale, c[3] * scale);
            *(__nv_bfloat162*)&s_sc[(mrow + r4    ) * SROW + n0 + cq] = lo;
            *(__nv_bfloat162*)&s_sc[(mrow + r4 + 8) * SROW + n0 + cq] = hi;
        }
        if (ch + 2 < 16) {
            *(float4*)((char*)s_kb0 + row0 * (KROW*2) + c80 * 16) = rA;
        }
        __syncthreads();
    }

    // ---- phase 2: warp w owns row w (32 warps, 32 rows) --------------------
    const unsigned* scrow = (const unsigned*)(s_sc + w * SROW);  // 1024 u32

    float m = -3.0e38f;
#pragma unroll 8
    for (int jj = 0; jj < 32; jj++) {
        unsigned u = scrow[lane + (jj << 5)];
        m = fmaxf(m, fmaxf(bf16lo(u), bf16hi(u)));
    }
    m = warpMaxF(m);

    float thr = m - MARGIN;
    float z = 0.f, s1 = 0.f;
#pragma unroll 4
    for (int jj = 0; jj < 32; jj++) {
        int wi = lane + (jj << 5);
        unsigned u = scrow[wi];
        float a = bf16lo(u), bvv = bf16hi(u);
        float xa = a - m, xb = bvv - m;
        float pa = __expf(xa), pb = __expf(xb);
        z += pa + pb;
        s1 = fmaf(pa, xa, fmaf(pb, xb, s1));
        if (a >= thr) {
            int pos = atomicAdd(&s_cnt[w], 1);
            if (pos < CAP) s_idx[w * CAP + pos] = (unsigned short)(wi * 2);
        }
        if (bvv >= thr) {
            int pos = atomicAdd(&s_cnt[w], 1);
            if (pos < CAP) s_idx[w * CAP + pos] = (unsigned short)(wi * 2 + 1);
        }
    }
    z  = warpSumF(z);
    s1 = warpSumF(s1);
    float hent = logf(z) - s1 / z;   // approx entropy (tiny error, harmless)
    __syncwarp();
    int cnt = s_cnt[w];

    int b = bh >> 3, hd = bh & 7;
    float* outp = &g_attn[((size_t)(b * SS + q0 + w)) * DD + hd * DH + lane * 2];

    if (hent >= 1.2f && cnt <= CAP) {
        // rescue: exact fp32 scores for candidates; exact argmax + tie set
        const float* qrow = Q + w * DH;     // fp32 Q row (L2-resident)
        float q_lo = qrow[lane], q_hi = qrow[lane + 32];
        float m_ex = -3.0e38f;
        for (int t = 0; t < cnt; t++) {
            int j = s_idx[w * CAP + t];
            float part = fmaf(q_lo, KT[(size_t)lane * SS + j],
                              q_hi * KT[(size_t)(lane + 32) * SS + j]);
            float s = warpSumF(part) * scale;
            if (lane == 0) s_exv[w * CAP + t] = s;
            m_ex = fmaxf(m_ex, s);
        }
        __syncwarp();
        int tiec = 0;
        float a0 = 0.f, a1 = 0.f;
        int d0 = lane * 2;
        for (int t = 0; t < cnt; t++) {
            if (s_exv[w * CAP + t] == m_ex) {
                tiec++;
                int j = s_idx[w * CAP + t];
                float2 vv = *(const float2*)(V + (size_t)j * DH + d0);
                a0 += vv.x; a1 += vv.y;
            }
        }
        float wgt = 1.0f / ((float)tiec + EPSF * z);
        float2 o; o.x = a0 * wgt; o.y = a1 * wgt;
        *(float2*)outp = o;
    } else {
        // ---- cold exact fallback: full fp32 recompute, reference semantics -
        const float* qrow = Q + w * DH;
        float fb[64];
        for (int jj = 0; jj < 64; jj++) {
            int j = lane + (jj << 5);
            float s = 0.f;
            for (int d = 0; d < DH; d++)
                s = fmaf(qrow[d], KT[(size_t)d * SS + j], s);
            fb[jj] = s * scale;
        }
        float m2 = -3.0e38f;
        for (int jj = 0; jj < 64; jj++) m2 = fmaxf(m2, fb[jj]);
        m2 = warpMaxF(m2);
        float z2 = 0.f;
        for (int jj = 0; jj < 64; jj++) z2 += expf(fb[jj] - m2);
        z2 = warpSumF(z2);
        float invZ = 1.0f / z2;
        float he = 0.f;
        for (int jj = 0; jj < 64; jj++) {
            float p  = expf(fb[jj] - m2);
            float ww = p * invZ;
            he -= ww * logf(ww + EPSF);
        }
        he = warpSumF(he);
        int tk = (int)(32.0f * (1.0f - he));
        tk = tk < 1 ? 1 : (tk > MAXK ? MAXK : tk);

        unsigned thr_u;
        if (tk == 1) {
            thr_u = ordf(m2);
        } else {
            thr_u = 0xFFFFFFFFu;
            int removed = 0;
            while (removed < tk) {
                unsigned best = 0u;
                for (int jj = 0; jj < 64; jj++) {
                    unsigned u = ordf(fb[jj]);
                    if (u < thr_u && u > best) best = u;
                }
                best = warpMaxU(best);
                int c = 0;
                for (int jj = 0; jj < 64; jj++) c += (ordf(fb[jj]) == best);
                c = warpSumI(c);
                removed += c;
                thr_u = best;
            }
        }

        float P = 0.f;
        for (int jj = 0; jj < 64; jj++)
            if (ordf(fb[jj]) >= thr_u) P += expf(fb[jj] - m2);
        P = warpSumF(P);
        float invDen = 1.0f / (P + EPSF * z2);

        float r0 = 0.f, r1 = 0.f;
        for (int dd = 0; dd < DH; dd += 2) {
            float a0 = 0.f, a1 = 0.f;
            for (int jj = 0; jj < 64; jj++) {
                float s = fb[jj];
                if (ordf(s) >= thr_u) {
                    int j = lane + (jj << 5);
                    float p = expf(s - m2);
                    float2 vv = *(const float2*)(V + (size_t)j * DH + dd);
                    a0 = fmaf(p, vv.x, a0);
                    a1 = fmaf(p, vv.y, a1);
                }
            }
            a0 = warpSumF(a0);
            a1 = warpSumF(a1);
            if (lane == (dd >> 1)) { r0 = a0; r1 = a1; }
        }
        float2 o; o.x = r0 * invDen; o.y = r1 * invDen;
        *(float2*)outp = o;
    }
}

// ---------------- launch -----------------------------------------------------
extern "C" void kernel_launch(void* const* d_in, const int* in_sizes, int n_in,
                              void* d_out, int out_size)
{
    const float* x     = (const float*)d_in[0];
    const float* w_in  = (const float*)d_in[1];
    const float* b_in  = (const float*)d_in[2];
    const float* w_out = (const float*)d_in[3];
    const float* b_out = (const float*)d_in[4];
    float* out = (float*)d_out;

    float* pattn = nullptr;
    cudaGetSymbolAddress((void**)&pattn, g_attn);

    cudaFuncSetAttribute(attn_kernel,
                         cudaFuncAttributeMaxDynamicSharedMemorySize, ATTN_SMEM);

    // 1) QKV projection with head-layout scatter (768 blocks of 128x64)
    sgemm_nt<1><<<dim3((3*DD)/64, (BB*SS)/128), 256>>>(
        x, w_in, b_in, nullptr, BB*SS, 3*DD, DD);

    // 2) fused attention: TQ=32 pipelined smem-staged tensor-core scores
    attn_kernel<<<dim3(SS/TQ, BH), ATHREADS, ATTN_SMEM>>>();

    // 3) output projection (512 blocks of 64x64 — full-wave packing)
    sgemm64<<<dim3(DD/64, (BB*SS)/64), 256>>>(
        pattn, w_out, b_out, out, BB*SS, DD, DD);
}

// round 15
// speedup vs baseline: 1.0168x; 1.0168x over previous
#include <cuda_runtime.h>
#include <cuda_bf16.h>
#include <cstdint>
#include <math.h>

// Problem constants (fixed by the dataset)
#define BB 2
#define SS 2048
#define DD 512
#define HH 8
#define DH 64
#define BH (BB*HH)          // 16
#define MAXK 32
#define EPSF 1e-8f

// ---------------- scratch (static device globals; no allocs allowed) --------
__device__ float        g_q  [BB*HH*SS*DH];   // [B,H,S,64] fp32
__device__ float        g_kT [BB*HH*DH*SS];   // [B,H,64,S] fp32 (exact rescue)
__device__ __nv_bfloat16 g_kb[BB*HH*SS*DH];   // [B,H,S,64] bf16 (mma B operand)
__device__ float        g_v  [BB*HH*SS*DH];   // [B,H,S,64]
__device__ float        g_attn[BB*SS*DD];     // [B,S,D]

// ---------------- warp reduce helpers ---------------------------------------
__device__ __forceinline__ float warpMaxF(float v){
#pragma unroll
    for (int o = 16; o; o >>= 1) v = fmaxf(v, __shfl_xor_sync(0xffffffffu, v, o));
    return v;
}
__device__ __forceinline__ float warpSumF(float v){
#pragma unroll
    for (int o = 16; o; o >>= 1) v += __shfl_xor_sync(0xffffffffu, v, o);
    return v;
}
__device__ __forceinline__ unsigned warpMaxU(unsigned v){
#pragma unroll
    for (int o = 16; o; o >>= 1) { unsigned t = __shfl_xor_sync(0xffffffffu, v, o); v = t > v ? t : v; }
    return v;
}
__device__ __forceinline__ int warpSumI(int v){
#pragma unroll
    for (int o = 16; o; o >>= 1) v += __shfl_xor_sync(0xffffffffu, v, o);
    return v;
}
__device__ __forceinline__ unsigned ordf(float f){
    unsigned u = __float_as_uint(f);
    return (u & 0x80000000u) ? ~u : (u | 0x80000000u);
}
__device__ __forceinline__ float bf16lo(unsigned u){ return __uint_as_float(u << 16); }
__device__ __forceinline__ float bf16hi(unsigned u){ return __uint_as_float(u & 0xffff0000u); }

// Schraudolph fast exp: ~±3% rel error, FMA/ALU pipes only (no MUFU).
// Valid for x in [-80, 80]; our x = s - m is in [-~20, 0].
__device__ __forceinline__ float fexp(float x){
    return __int_as_float((int)fmaf(12102203.0f, x, 1064866805.0f));
}

// bf16 mma m16n8k16: D = A(16x16,row) * B(16x8,col) + C, fp32 accum
__device__ __forceinline__ void mma16816(float c[4], const unsigned a[4],
                                         unsigned b0, unsigned b1){
    asm volatile(
        "mma.sync.aligned.m16n8k16.row.col.f32.bf16.bf16.f32 "
        "{%0,%1,%2,%3}, {%4,%5,%6,%7}, {%8,%9}, {%0,%1,%2,%3};"
        : "+f"(c[0]), "+f"(c[1]), "+f"(c[2]), "+f"(c[3])
        : "r"(a[0]), "r"(a[1]), "r"(a[2]), "r"(a[3]), "r"(b0), "r"(b1));
}

// ---------------- SGEMM: C[M,N] = A[M,K] * Bw[N,K]^T + bias ------------------
// BM=128 x BN=64 tiles, double-buffered, 3 CTAs/SM (R8-proven).
// MODE 0: plain store. MODE 1: q/kT/kb/v scatter.
template<int MODE>
__global__ __launch_bounds__(256, 3)
void sgemm_nt(const float* __restrict__ A, const float* __restrict__ Bw,
              const float* __restrict__ bias, float* __restrict__ C,
              int M, int N, int K)
{
    const int BM = 128, BN = 64, BK = 16;
    __shared__ float As[2][BK][BM + 4];
    __shared__ float Bs[2][BK][BN + 4];

    int tid = threadIdx.x;
    int tx = tid & 15, ty = tid >> 4;
    int bm = blockIdx.y * BM, bn = blockIdx.x * BN;

    int arow0 = tid >> 2, ac = (tid & 3) * 4;
    int arow1 = arow0 + 64;
    int brow  = tid >> 2, bc = ac;

    float acc[8][4];
#pragma unroll
    for (int i = 0; i < 8; i++)
#pragma unroll
        for (int j = 0; j < 4; j++) acc[i][j] = 0.f;

    const float* Ab = A + (size_t)bm * K;
    const float* Bb = Bw + (size_t)bn * K;

    float4 pa0, pa1, pb0;

    pa0 = *(const float4*)(Ab + (size_t)arow0 * K + ac);
    pa1 = *(const float4*)(Ab + (size_t)arow1 * K + ac);
    pb0 = *(const float4*)(Bb + (size_t)brow  * K + bc);
    As[0][ac+0][arow0]=pa0.x; As[0][ac+1][arow0]=pa0.y; As[0][ac+2][arow0]=pa0.z; As[0][ac+3][arow0]=pa0.w;
    As[0][ac+0][arow1]=pa1.x; As[0][ac+1][arow1]=pa1.y; As[0][ac+2][arow1]=pa1.z; As[0][ac+3][arow1]=pa1.w;
    Bs[0][bc+0][brow ]=pb0.x; Bs[0][bc+1][brow ]=pb0.y; Bs[0][bc+2][brow ]=pb0.z; Bs[0][bc+3][brow ]=pb0.w;
    __syncthreads();

    for (int k0 = 0; k0 < K; k0 += BK) {
        int buf = (k0 >> 4) & 1;
        bool more = (k0 + BK) < K;
        if (more) {
            int kn = k0 + BK;
            pa0 = *(const float4*)(Ab + (size_t)arow0 * K + kn + ac);
            pa1 = *(const float4*)(Ab + (size_t)arow1 * K + kn + ac);
            pb0 = *(const float4*)(Bb + (size_t)brow  * K + kn + bc);
        }
#pragma unroll
        for (int k = 0; k < BK; k++) {
            float4 a0 = *(const float4*)&As[buf][k][ty * 8];
            float4 a1 = *(const float4*)&As[buf][k][ty * 8 + 4];
            float4 b0 = *(const float4*)&Bs[buf][k][tx * 4];
            float av[8] = {a0.x,a0.y,a0.z,a0.w,a1.x,a1.y,a1.z,a1.w};
            float bv[4] = {b0.x,b0.y,b0.z,b0.w};
#pragma unroll
            for (int i = 0; i < 8; i++)
#pragma unroll
                for (int j = 0; j < 4; j++) acc[i][j] = fmaf(av[i], bv[j], acc[i][j]);
        }
        if (more) {
            int nb = buf ^ 1;
            As[nb][ac+0][arow0]=pa0.x; As[nb][ac+1][arow0]=pa0.y; As[nb][ac+2][arow0]=pa0.z; As[nb][ac+3][arow0]=pa0.w;
            As[nb][ac+0][arow1]=pa1.x; As[nb][ac+1][arow1]=pa1.y; As[nb][ac+2][arow1]=pa1.z; As[nb][ac+3][arow1]=pa1.w;
            Bs[nb][bc+0][brow ]=pb0.x; Bs[nb][bc+1][brow ]=pb0.y; Bs[nb][bc+2][brow ]=pb0.z; Bs[nb][bc+3][brow ]=pb0.w;
        }
        __syncthreads();
    }

    if (MODE == 0) {
#pragma unroll
        for (int i = 0; i < 8; i++) {
            int mrow = bm + ty * 8 + i;
            int col = bn + tx * 4;
            float4 bv = *(const float4*)(bias + col);
            float4 o;
            o.x = acc[i][0] + bv.x; o.y = acc[i][1] + bv.y;
            o.z = acc[i][2] + bv.z; o.w = acc[i][3] + bv.w;
            *(float4*)(C + (size_t)mrow * N + col) = o;
        }
    } else {
#pragma unroll
        for (int i = 0; i < 8; i++) {
            int mrow = bm + ty * 8 + i;
            int b = mrow >> 11;          // S = 2048
            int s = mrow & 2047;
#pragma unroll
            for (int j = 0; j < 4; j++) {
                int n = bn + tx * 4 + j;
                float val = acc[i][j] + bias[n];
                int sec = n >> 9;        // 0:q 1:k 2:v (D = 512)
                int nn  = n & 511;
                int head = nn >> 6, d = nn & 63;
                size_t sd = ((size_t)((b*HH+head)*SS) + s)*DH + d;
                if (sec == 0) {
                    g_q[sd] = val;
                } else if (sec == 1) {
                    g_kT[((size_t)((b*HH+head)*DH) + d)*SS + s] = val;
                    g_kb[sd] = __float2bfloat16(val);
                } else {
                    g_v[sd] = val;
                }
            }
        }
    }
}

// ---------------- fused attention v9: v7 + MUFU-free Z/S1 sweep --------------
// Identical to R13's v7 (TQ=16, 2 CTAs/SM, double-buffered staging) except the
// phase-2 Z/S1 sweep uses Schraudolph fast-exp (fp/alu pipes) instead of
// __expf (MUFU). H slack ~6 units and EPS*Z effect ~1.5e-7 make the ±3% error
// harmless; rescue/fallback keep true expf.
#define TQ 16
#define ATHREADS 512
#define CAP 64
#define MARGIN 0.05f
#define SROW 2056                        // bf16 per score row (2048 + 8 pad)
#define KROW 72                          // bf16 per staged K row (64 + 8 pad)

#define OFF_KB0 (TQ*SROW*2)              // 65792
#define OFF_KB1 (OFF_KB0 + 128*KROW*2)   // + 18432
#define OFF_QB  (OFF_KB1 + 128*KROW*2)   // + 18432
#define OFF_CNT (OFF_QB + TQ*DH*2)       // + 2048
#define OFF_IDX (OFF_CNT + 64)
#define OFF_EXV (OFF_IDX + TQ*CAP*2)
#define ATTN_SMEM (OFF_EXV + TQ*CAP*4)   // = 110912 bytes

__global__ __launch_bounds__(ATHREADS, 2)
void attn_kernel()
{
    extern __shared__ unsigned char smem[];
    unsigned short* s_sc = (unsigned short*)smem;             // [16][SROW]
    __nv_bfloat16* s_kb0 = (__nv_bfloat16*)(smem + OFF_KB0);  // [128][KROW]
    __nv_bfloat16* s_kb1 = (__nv_bfloat16*)(smem + OFF_KB1);  // [128][KROW]
    __nv_bfloat16* s_qb = (__nv_bfloat16*)(smem + OFF_QB);    // [16][64]
    int*   s_cnt = (int*)(smem + OFF_CNT);                    // [16]
    unsigned short* s_idx = (unsigned short*)(smem + OFF_IDX);// [16][CAP]
    float* s_exv = (float*)(smem + OFF_EXV);                  // [16][CAP]

    int bh = blockIdx.y;
    int q0 = blockIdx.x * TQ;
    const float* Q  = g_q  + ((size_t)bh * SS + q0) * DH;
    const float* KT = g_kT + (size_t)bh * DH * SS;
    const __nv_bfloat16* Kb = g_kb + (size_t)bh * SS * DH;
    const float* V  = g_v  + (size_t)bh * SS * DH;
    int tid = threadIdx.x;
    int lane = tid & 31, w = tid >> 5;

    // load Q tile bf16 copy
    for (int e = tid; e < TQ * DH; e += ATHREADS)
        s_qb[e] = __float2bfloat16(Q[e]);
    if (tid < TQ) s_cnt[tid] = 0;
    __syncthreads();

    const float scale = 0.125f;   // 1/sqrt(64)
    int r4 = lane >> 2, cq = (lane & 3) * 2;

    // A fragments (Q), persistent across chunks
    unsigned afr[4][4];
#pragma unroll
    for (int kk = 0; kk < 4; kk++) {
        int cb = kk * 16 + cq;
        afr[kk][0] = *(const unsigned*)&s_qb[ r4      * DH + cb    ];
        afr[kk][1] = *(const unsigned*)&s_qb[(r4 + 8) * DH + cb    ];
        afr[kk][2] = *(const unsigned*)&s_qb[ r4      * DH + cb + 8];
        afr[kk][3] = *(const unsigned*)&s_qb[(r4 + 8) * DH + cb + 8];
    }

    // staging lane geometry (2 float4 per thread per 128-row chunk)
    int row0 = tid >> 3,            c80 = tid & 7;
    int row1 = (tid + ATHREADS) >> 3, c81 = c80;

    // ---- phase 1: 16 chunks of 128 K-rows, double-buffered -----------------
    float4 rA0, rA1, rB0, rB1;
    rA0 = *(const float4*)(Kb + ((size_t)(row0)) * DH + c80 * 8);
    rA1 = *(const float4*)(Kb + ((size_t)(row1)) * DH + c81 * 8);
    *(float4*)((char*)s_kb0 + row0 * (KROW*2) + c80 * 16) = rA0;
    *(float4*)((char*)s_kb0 + row1 * (KROW*2) + c81 * 16) = rA1;
    rB0 = *(const float4*)(Kb + ((size_t)(128 + row0)) * DH + c80 * 8);
    rB1 = *(const float4*)(Kb + ((size_t)(128 + row1)) * DH + c81 * 8);
    __syncthreads();

#pragma unroll
    for (int ch = 0; ch < 16; ch += 2) {
        if (ch + 2 < 16) {
            rA0 = *(const float4*)(Kb + ((size_t)((ch+2)*128 + row0)) * DH + c80 * 8);
            rA1 = *(const float4*)(Kb + ((size_t)((ch+2)*128 + row1)) * DH + c81 * 8);
        }
        {
            float c[4] = {0.f, 0.f, 0.f, 0.f};
            const __nv_bfloat16* kbp = s_kb0 + (w * 8 + r4) * KROW + cq;
#pragma unroll
            for (int kk = 0; kk < 4; kk++) {
                unsigned b0 = *(const unsigned*)(kbp + kk * 16);
                unsigned b1 = *(const unsigned*)(kbp + kk * 16 + 8);
                mma16816(c, afr[kk], b0, b1);
            }
            int n0 = ch * 128 + w * 8;
            __nv_bfloat162 lo = __floats2bfloat162_rn(c[0] * scale, c[1] * scale);
            __nv_bfloat162 hi = __floats2bfloat162_rn(c[2] * scale, c[3] * scale);
            *(__nv_bfloat162*)&s_sc[ r4      * SROW + n0 + cq] = lo;
            *(__nv_bfloat162*)&s_sc[(r4 + 8) * SROW + n0 + cq] = hi;
        }
        *(float4*)((char*)s_kb1 + row0 * (KROW*2) + c80 * 16) = rB0;
        *(float4*)((char*)s_kb1 + row1 * (KROW*2) + c81 * 16) = rB1;
        __syncthreads();

        if (ch + 3 < 16) {
            rB0 = *(const float4*)(Kb + ((size_t)((ch+3)*128 + row0)) * DH + c80 * 8);
            rB1 = *(const float4*)(Kb + ((size_t)((ch+3)*128 + row1)) * DH + c81 * 8);
        }
        {
            float c[4] = {0.f, 0.f, 0.f, 0.f};
            const __nv_bfloat16* kbp = s_kb1 + (w * 8 + r4) * KROW + cq;
#pragma unroll
            for (int kk = 0; kk < 4; kk++) {
                unsigned b0 = *(const unsigned*)(kbp + kk * 16);
                unsigned b1 = *(const unsigned*)(kbp + kk * 16 + 8);
                mma16816(c, afr[kk], b0, b1);
            }
            int n0 = (ch + 1) * 128 + w * 8;
            __nv_bfloat162 lo = __floats2bfloat162_rn(c[0] * scale, c[1] * scale);
            __nv_bfloat162 hi = __floats2bfloat162_rn(c[2] * scale, c[3] * scale);
            *(__nv_bfloat162*)&s_sc[ r4      * SROW + n0 + cq] = lo;
            *(__nv_bfloat162*)&s_sc[(r4 + 8) * SROW + n0 + cq] = hi;
        }
        if (ch + 2 < 16) {
            *(float4*)((char*)s_kb0 + row0 * (KROW*2) + c80 * 16) = rA0;
            *(float4*)((char*)s_kb0 + row1 * (KROW*2) + c81 * 16) = rA1;
        }
        __syncthreads();
    }

    // ---- phase 2: warp w owns row w ----------------------------------------
    const unsigned* scrow = (const unsigned*)(s_sc + w * SROW);  // 1024 u32

    float m = -3.0e38f;
#pragma unroll 8
    for (int jj = 0; jj < 32; jj++) {
        unsigned u = scrow[lane + (jj << 5)];
        m = fmaxf(m, fmaxf(bf16lo(u), bf16hi(u)));
    }
    m = warpMaxF(m);

    float thr = m - MARGIN;
    float z = 0.f, s1 = 0.f;
#pragma unroll 4
    for (int jj = 0; jj < 32; jj++) {
        int wi = lane + (jj << 5);
        unsigned u = scrow[wi];
        float a = bf16lo(u), bvv = bf16hi(u);
        float xa = a - m, xb = bvv - m;
        float pa = fexp(xa), pb = fexp(xb);   // MUFU-free fast exp
        z += pa + pb;
        s1 = fmaf(pa, xa, fmaf(pb, xb, s1));
        if (a >= thr) {
            int pos = atomicAdd(&s_cnt[w], 1);
            if (pos < CAP) s_idx[w * CAP + pos] = (unsigned short)(wi * 2);
        }
        if (bvv >= thr) {
            int pos = atomicAdd(&s_cnt[w], 1);
            if (pos < CAP) s_idx[w * CAP + pos] = (unsigned short)(wi * 2 + 1);
        }
    }
    z  = warpSumF(z);
    s1 = warpSumF(s1);
    float hent = logf(z) - s1 / z;   // approx entropy (slack ~6 vs 1.2 gate)
    __syncwarp();
    int cnt = s_cnt[w];

    int b = bh >> 3, hd = bh & 7;
    float* outp = &g_attn[((size_t)(b * SS + q0 + w)) * DD + hd * DH + lane * 2];

    if (hent >= 1.2f && cnt <= CAP) {
        // rescue: exact fp32 scores for candidates; exact argmax + tie set
        const float* qrow = Q + w * DH;     // fp32 Q row (L2-resident)
        float q_lo = qrow[lane], q_hi = qrow[lane + 32];
        float m_ex = -3.0e38f;
        for (int t = 0; t < cnt; t++) {
            int j = s_idx[w * CAP + t];
            float part = fmaf(q_lo, KT[(size_t)lane * SS + j],
                              q_hi * KT[(size_t)(lane + 32) * SS + j]);
            float s = warpSumF(part) * scale;
            if (lane == 0) s_exv[w * CAP + t] = s;
            m_ex = fmaxf(m_ex, s);
        }
        __syncwarp();
        int tiec = 0;
        float a0 = 0.f, a1 = 0.f;
        int d0 = lane * 2;
        for (int t = 0; t < cnt; t++) {
            if (s_exv[w * CAP + t] == m_ex) {
                tiec++;
                int j = s_idx[w * CAP + t];
                float2 vv = *(const float2*)(V + (size_t)j * DH + d0);
                a0 += vv.x; a1 += vv.y;
            }
        }
        float wgt = 1.0f / ((float)tiec + EPSF * z);
        float2 o; o.x = a0 * wgt; o.y = a1 * wgt;
        *(float2*)outp = o;
    } else {
        // ---- cold exact fallback: full fp32 recompute, reference semantics -
        const float* qrow = Q + w * DH;
        float fb[64];
        for (int jj = 0; jj < 64; jj++) {
            int j = lane + (jj << 5);
            float s = 0.f;
            for (int d = 0; d < DH; d++)
                s = fmaf(qrow[d], KT[(size_t)d * SS + j], s);
            fb[jj] = s * scale;
        }
        float m2 = -3.0e38f;
        for (int jj = 0; jj < 64; jj++) m2 = fmaxf(m2, fb[jj]);
        m2 = warpMaxF(m2);
        float z2 = 0.f;
        for (int jj = 0; jj < 64; jj++) z2 += expf(fb[jj] - m2);
        z2 = warpSumF(z2);
        float invZ = 1.0f / z2;
        float he = 0.f;
        for (int jj = 0; jj < 64; jj++) {
            float p  = expf(fb[jj] - m2);
            float ww = p * invZ;
            he -= ww * logf(ww + EPSF);
        }
        he = warpSumF(he);
        int tk = (int)(32.0f * (1.0f - he));
        tk = tk < 1 ? 1 : (tk > MAXK ? MAXK : tk);

        unsigned thr_u;
        if (tk == 1) {
            thr_u = ordf(m2);
        } else {
            thr_u = 0xFFFFFFFFu;
            int removed = 0;
            while (removed < tk) {
                unsigned best = 0u;
                for (int jj = 0; jj < 64; jj++) {
                    unsigned u = ordf(fb[jj]);
                    if (u < thr_u && u > best) best = u;
                }
                best = warpMaxU(best);
                int c = 0;
                for (int jj = 0; jj < 64; jj++) c += (ordf(fb[jj]) == best);
                c = warpSumI(c);
                removed += c;
                thr_u = best;
            }
        }

        float P = 0.f;
        for (int jj = 0; jj < 64; jj++)
            if (ordf(fb[jj]) >= thr_u) P += expf(fb[jj] - m2);
        P = warpSumF(P);
        float invDen = 1.0f / (P + EPSF * z2);

        float r0 = 0.f, r1 = 0.f;
        for (int dd = 0; dd < DH; dd += 2) {
            float a0 = 0.f, a1 = 0.f;
            for (int jj = 0; jj < 64; jj++) {
                float s = fb[jj];
                if (ordf(s) >= thr_u) {
                    int j = lane + (jj << 5);
                    float p = expf(s - m2);
                    float2 vv = *(const float2*)(V + (size_t)j * DH + dd);
                    a0 = fmaf(p, vv.x, a0);
                    a1 = fmaf(p, vv.y, a1);
                }
            }
            a0 = warpSumF(a0);
            a1 = warpSumF(a1);
            if (lane == (dd >> 1)) { r0 = a0; r1 = a1; }
        }
        float2 o; o.x = r0 * invDen; o.y = r1 * invDen;
        *(float2*)outp = o;
    }
}

// ---------------- launch -----------------------------------------------------
extern "C" void kernel_launch(void* const* d_in, const int* in_sizes, int n_in,
                              void* d_out, int out_size)
{
    const float* x     = (const float*)d_in[0];
    const float* w_in  = (const float*)d_in[1];
    const float* b_in  = (const float*)d_in[2];
    const float* w_out = (const float*)d_in[3];
    const float* b_out = (const float*)d_in[4];
    float* out = (float*)d_out;

    float* pattn = nullptr;
    cudaGetSymbolAddress((void**)&pattn, g_attn);

    cudaFuncSetAttribute(attn_kernel,
                         cudaFuncAttributeMaxDynamicSharedMemorySize, ATTN_SMEM);

    // 1) QKV projection with head-layout scatter (768 blocks of 128x64)
    sgemm_nt<1><<<dim3((3*DD)/64, (BB*SS)/128), 256>>>(
        x, w_in, b_in, nullptr, BB*SS, 3*DD, DD);

    // 2) fused attention: pipelined mma scores + MUFU-free stats sweep
    attn_kernel<<<dim3(SS/TQ, BH), ATHREADS, ATTN_SMEM>>>();

    // 3) output projection (256 blocks of 128x64)
    sgemm_nt<0><<<dim3(DD/64, (BB*SS)/128), 256>>>(
        pattn, w_out, b_out, out, BB*SS, DD, DD);
}

// round 16
// speedup vs baseline: 1.0330x; 1.0160x over previous
#include <cuda_runtime.h>
#include <cuda_bf16.h>
#include <cstdint>
#include <math.h>

// Problem constants (fixed by the dataset)
#define BB 2
#define SS 2048
#define DD 512
#define HH 8
#define DH 64
#define BH (BB*HH)          // 16
#define MAXK 32
#define EPSF 1e-8f

// ---------------- scratch (static device globals; no allocs allowed) --------
__device__ float        g_q  [BB*HH*SS*DH];   // [B,H,S,64] fp32
__device__ float        g_kT [BB*HH*DH*SS];   // [B,H,64,S] fp32 (exact rescue)
__device__ __nv_bfloat16 g_kb[BB*HH*SS*DH];   // [B,H,S,64] bf16 (mma B operand)
__device__ float        g_v  [BB*HH*SS*DH];   // [B,H,S,64]
__device__ float        g_attn[BB*SS*DD];     // [B,S,D]

// ---------------- warp reduce helpers ---------------------------------------
__device__ __forceinline__ float warpMaxF(float v){
#pragma unroll
    for (int o = 16; o; o >>= 1) v = fmaxf(v, __shfl_xor_sync(0xffffffffu, v, o));
    return v;
}
__device__ __forceinline__ float warpSumF(float v){
#pragma unroll
    for (int o = 16; o; o >>= 1) v += __shfl_xor_sync(0xffffffffu, v, o);
    return v;
}
__device__ __forceinline__ unsigned warpMaxU(unsigned v){
#pragma unroll
    for (int o = 16; o; o >>= 1) { unsigned t = __shfl_xor_sync(0xffffffffu, v, o); v = t > v ? t : v; }
    return v;
}
__device__ __forceinline__ int warpSumI(int v){
#pragma unroll
    for (int o = 16; o; o >>= 1) v += __shfl_xor_sync(0xffffffffu, v, o);
    return v;
}
__device__ __forceinline__ unsigned ordf(float f){
    unsigned u = __float_as_uint(f);
    return (u & 0x80000000u) ? ~u : (u | 0x80000000u);
}
__device__ __forceinline__ float bf16lo(unsigned u){ return __uint_as_float(u << 16); }
__device__ __forceinline__ float bf16hi(unsigned u){ return __uint_as_float(u & 0xffff0000u); }

// Schraudolph fast exp: ~±3% rel error, FMA/ALU pipes only (no MUFU).
__device__ __forceinline__ float fexp(float x){
    return __int_as_float((int)fmaf(12102203.0f, x, 1064866805.0f));
}

// bf16 mma m16n8k16: D = A(16x16,row) * B(16x8,col) + C, fp32 accum
__device__ __forceinline__ void mma16816(float c[4], const unsigned a[4],
                                         unsigned b0, unsigned b1){
    asm volatile(
        "mma.sync.aligned.m16n8k16.row.col.f32.bf16.bf16.f32 "
        "{%0,%1,%2,%3}, {%4,%5,%6,%7}, {%8,%9}, {%0,%1,%2,%3};"
        : "+f"(c[0]), "+f"(c[1]), "+f"(c[2]), "+f"(c[3])
        : "r"(a[0]), "r"(a[1]), "r"(a[2]), "r"(a[3]), "r"(b0), "r"(b1));
}

// ---------------- SGEMM: C[M,N] = A[M,K] * Bw[N,K]^T + bias ------------------
// BM=128 x BN=64 tiles, double-buffered, 3 CTAs/SM (R8-proven).
// MODE 0: plain store. MODE 1: q/kT/kb/v scatter.
template<int MODE>
__global__ __launch_bounds__(256, 3)
void sgemm_nt(const float* __restrict__ A, const float* __restrict__ Bw,
              const float* __restrict__ bias, float* __restrict__ C,
              int M, int N, int K)
{
    const int BM = 128, BN = 64, BK = 16;
    __shared__ float As[2][BK][BM + 4];
    __shared__ float Bs[2][BK][BN + 4];

    int tid = threadIdx.x;
    int tx = tid & 15, ty = tid >> 4;
    int bm = blockIdx.y * BM, bn = blockIdx.x * BN;

    int arow0 = tid >> 2, ac = (tid & 3) * 4;
    int arow1 = arow0 + 64;
    int brow  = tid >> 2, bc = ac;

    float acc[8][4];
#pragma unroll
    for (int i = 0; i < 8; i++)
#pragma unroll
        for (int j = 0; j < 4; j++) acc[i][j] = 0.f;

    const float* Ab = A + (size_t)bm * K;
    const float* Bb = Bw + (size_t)bn * K;

    float4 pa0, pa1, pb0;

    pa0 = *(const float4*)(Ab + (size_t)arow0 * K + ac);
    pa1 = *(const float4*)(Ab + (size_t)arow1 * K + ac);
    pb0 = *(const float4*)(Bb + (size_t)brow  * K + bc);
    As[0][ac+0][arow0]=pa0.x; As[0][ac+1][arow0]=pa0.y; As[0][ac+2][arow0]=pa0.z; As[0][ac+3][arow0]=pa0.w;
    As[0][ac+0][arow1]=pa1.x; As[0][ac+1][arow1]=pa1.y; As[0][ac+2][arow1]=pa1.z; As[0][ac+3][arow1]=pa1.w;
    Bs[0][bc+0][brow ]=pb0.x; Bs[0][bc+1][brow ]=pb0.y; Bs[0][bc+2][brow ]=pb0.z; Bs[0][bc+3][brow ]=pb0.w;
    __syncthreads();

    for (int k0 = 0; k0 < K; k0 += BK) {
        int buf = (k0 >> 4) & 1;
        bool more = (k0 + BK) < K;
        if (more) {
            int kn = k0 + BK;
            pa0 = *(const float4*)(Ab + (size_t)arow0 * K + kn + ac);
            pa1 = *(const float4*)(Ab + (size_t)arow1 * K + kn + ac);
            pb0 = *(const float4*)(Bb + (size_t)brow  * K + kn + bc);
        }
#pragma unroll
        for (int k = 0; k < BK; k++) {
            float4 a0 = *(const float4*)&As[buf][k][ty * 8];
            float4 a1 = *(const float4*)&As[buf][k][ty * 8 + 4];
            float4 b0 = *(const float4*)&Bs[buf][k][tx * 4];
            float av[8] = {a0.x,a0.y,a0.z,a0.w,a1.x,a1.y,a1.z,a1.w};
            float bv[4] = {b0.x,b0.y,b0.z,b0.w};
#pragma unroll
            for (int i = 0; i < 8; i++)
#pragma unroll
                for (int j = 0; j < 4; j++) acc[i][j] = fmaf(av[i], bv[j], acc[i][j]);
        }
        if (more) {
            int nb = buf ^ 1;
            As[nb][ac+0][arow0]=pa0.x; As[nb][ac+1][arow0]=pa0.y; As[nb][ac+2][arow0]=pa0.z; As[nb][ac+3][arow0]=pa0.w;
            As[nb][ac+0][arow1]=pa1.x; As[nb][ac+1][arow1]=pa1.y; As[nb][ac+2][arow1]=pa1.z; As[nb][ac+3][arow1]=pa1.w;
            Bs[nb][bc+0][brow ]=pb0.x; Bs[nb][bc+1][brow ]=pb0.y; Bs[nb][bc+2][brow ]=pb0.z; Bs[nb][bc+3][brow ]=pb0.w;
        }
        __syncthreads();
    }

    if (MODE == 0) {
#pragma unroll
        for (int i = 0; i < 8; i++) {
            int mrow = bm + ty * 8 + i;
            int col = bn + tx * 4;
            float4 bv = *(const float4*)(bias + col);
            float4 o;
            o.x = acc[i][0] + bv.x; o.y = acc[i][1] + bv.y;
            o.z = acc[i][2] + bv.z; o.w = acc[i][3] + bv.w;
            *(float4*)(C + (size_t)mrow * N + col) = o;
        }
    } else {
#pragma unroll
        for (int i = 0; i < 8; i++) {
            int mrow = bm + ty * 8 + i;
            int b = mrow >> 11;          // S = 2048
            int s = mrow & 2047;
#pragma unroll
            for (int j = 0; j < 4; j++) {
                int n = bn + tx * 4 + j;
                float val = acc[i][j] + bias[n];
                int sec = n >> 9;        // 0:q 1:k 2:v (D = 512)
                int nn  = n & 511;
                int head = nn >> 6, d = nn & 63;
                size_t sd = ((size_t)((b*HH+head)*SS) + s)*DH + d;
                if (sec == 0) {
                    g_q[sd] = val;
                } else if (sec == 1) {
                    g_kT[((size_t)((b*HH+head)*DH) + d)*SS + s] = val;
                    g_kb[sd] = __float2bfloat16(val);
                } else {
                    g_v[sd] = val;
                }
            }
        }
    }
}

// ---------------- fused attention v10: warp-autonomous phase 1 ---------------
// Key insight: warp w's mma consumes ONLY K rows w*8..w*8+7 of each staged
// chunk -> no cross-warp sharing -> no block barriers needed in phase 1.
// Each warp privately stages its 8 rows (2 coalesced float4 LDGs = 4
// contiguous rows each), double-buffered in its own smem slice, one
// __syncwarp per chunk. Single __syncthreads before phase 2 (which is
// cross-warp: warp w reads score row w written by all warps).
// Phase 2 / rescue / fallback identical to R15 (proven numerics).
#define TQ 16
#define ATHREADS 512
#define CAP 64
#define MARGIN 0.05f
#define SROW 2056                        // bf16 per score row (2048 + 8 pad)
#define KROW 72                          // bf16 per staged K row (64 + 8 pad)
#define KWSLICE (2*8*KROW)               // per-warp: 2 bufs x 8 rows x KROW

#define OFF_KW  (TQ*SROW*2)              // 65792
#define OFF_QB  (OFF_KW + 16*KWSLICE*2)  // + 36864
#define OFF_CNT (OFF_QB + TQ*DH*2)       // + 2048
#define OFF_IDX (OFF_CNT + 64)
#define OFF_EXV (OFF_IDX + TQ*CAP*2)
#define ATTN_SMEM (OFF_EXV + TQ*CAP*4)   // = 110912 bytes

__global__ __launch_bounds__(ATHREADS, 2)
void attn_kernel()
{
    extern __shared__ unsigned char smem[];
    unsigned short* s_sc = (unsigned short*)smem;             // [16][SROW]
    __nv_bfloat16* s_kw = (__nv_bfloat16*)(smem + OFF_KW);    // [16][2][8][KROW]
    __nv_bfloat16* s_qb = (__nv_bfloat16*)(smem + OFF_QB);    // [16][64]
    int*   s_cnt = (int*)(smem + OFF_CNT);                    // [16]
    unsigned short* s_idx = (unsigned short*)(smem + OFF_IDX);// [16][CAP]
    float* s_exv = (float*)(smem + OFF_EXV);                  // [16][CAP]

    int bh = blockIdx.y;
    int q0 = blockIdx.x * TQ;
    const float* Q  = g_q  + ((size_t)bh * SS + q0) * DH;
    const float* KT = g_kT + (size_t)bh * DH * SS;
    const __nv_bfloat16* Kb = g_kb + (size_t)bh * SS * DH;
    const float* V  = g_v  + (size_t)bh * SS * DH;
    int tid = threadIdx.x;
    int lane = tid & 31, w = tid >> 5;

    // load Q tile bf16 copy
    for (int e = tid; e < TQ * DH; e += ATHREADS)
        s_qb[e] = __float2bfloat16(Q[e]);
    if (tid < TQ) s_cnt[tid] = 0;
    __syncthreads();

    const float scale = 0.125f;   // 1/sqrt(64)
    int r4 = lane >> 2, cq = (lane & 3) * 2;

    // A fragments (Q), persistent across chunks
    unsigned afr[4][4];
#pragma unroll
    for (int kk = 0; kk < 4; kk++) {
        int cb = kk * 16 + cq;
        afr[kk][0] = *(const unsigned*)&s_qb[ r4      * DH + cb    ];
        afr[kk][1] = *(const unsigned*)&s_qb[(r4 + 8) * DH + cb    ];
        afr[kk][2] = *(const unsigned*)&s_qb[ r4      * DH + cb + 8];
        afr[kk][3] = *(const unsigned*)&s_qb[(r4 + 8) * DH + cb + 8];
    }

    // ---- phase 1: warp-autonomous, 16 chunks, private double buffer --------
    // lane l stages: row lr = l>>3 (and lr+4), float4 index lc8 = l&7.
    {
        int lr = lane >> 3, lc8 = lane & 7;
        __nv_bfloat16* myk = s_kw + w * KWSLICE;
        int n0base = w * 8;

        float4 p0, p1;
        p0 = *(const float4*)(Kb + (size_t)(n0base + lr    ) * DH + lc8 * 8);
        p1 = *(const float4*)(Kb + (size_t)(n0base + lr + 4) * DH + lc8 * 8);

#pragma unroll 4
        for (int ch = 0; ch < 16; ch++) {
            __nv_bfloat16* kb = myk + (ch & 1) * (8 * KROW);
            *(float4*)((char*)kb + (size_t)lr       * (KROW*2) + lc8 * 16) = p0;
            *(float4*)((char*)kb + (size_t)(lr + 4) * (KROW*2) + lc8 * 16) = p1;
            __syncwarp();
            if (ch + 1 < 16) {
                int nn = (ch + 1) * 128 + n0base;
                p0 = *(const float4*)(Kb + (size_t)(nn + lr    ) * DH + lc8 * 8);
                p1 = *(const float4*)(Kb + (size_t)(nn + lr + 4) * DH + lc8 * 8);
            }
            float c[4] = {0.f, 0.f, 0.f, 0.f};
            const __nv_bfloat16* kbp = kb + r4 * KROW + cq;
#pragma unroll
            for (int kk = 0; kk < 4; kk++) {
                unsigned b0 = *(const unsigned*)(kbp + kk * 16);
                unsigned b1 = *(const unsigned*)(kbp + kk * 16 + 8);
                mma16816(c, afr[kk], b0, b1);
            }
            int n0 = ch * 128 + n0base;
            __nv_bfloat162 lo = __floats2bfloat162_rn(c[0] * scale, c[1] * scale);
            __nv_bfloat162 hi = __floats2bfloat162_rn(c[2] * scale, c[3] * scale);
            *(__nv_bfloat162*)&s_sc[ r4      * SROW + n0 + cq] = lo;
            *(__nv_bfloat162*)&s_sc[(r4 + 8) * SROW + n0 + cq] = hi;
        }
    }
    __syncthreads();   // single block barrier: scores row w now complete

    // ---- phase 2: warp w owns row w ----------------------------------------
    const unsigned* scrow = (const unsigned*)(s_sc + w * SROW);  // 1024 u32

    float m = -3.0e38f;
#pragma unroll 8
    for (int jj = 0; jj < 32; jj++) {
        unsigned u = scrow[lane + (jj << 5)];
        m = fmaxf(m, fmaxf(bf16lo(u), bf16hi(u)));
    }
    m = warpMaxF(m);

    float thr = m - MARGIN;
    float z = 0.f, s1 = 0.f;
#pragma unroll 4
    for (int jj = 0; jj < 32; jj++) {
        int wi = lane + (jj << 5);
        unsigned u = scrow[wi];
        float a = bf16lo(u), bvv = bf16hi(u);
        float xa = a - m, xb = bvv - m;
        float pa = fexp(xa), pb = fexp(xb);   // MUFU-free fast exp
        z += pa + pb;
        s1 = fmaf(pa, xa, fmaf(pb, xb, s1));
        if (a >= thr) {
            int pos = atomicAdd(&s_cnt[w], 1);
            if (pos < CAP) s_idx[w * CAP + pos] = (unsigned short)(wi * 2);
        }
        if (bvv >= thr) {
            int pos = atomicAdd(&s_cnt[w], 1);
            if (pos < CAP) s_idx[w * CAP + pos] = (unsigned short)(wi * 2 + 1);
        }
    }
    z  = warpSumF(z);
    s1 = warpSumF(s1);
    float hent = logf(z) - s1 / z;   // approx entropy (slack ~6 vs 1.2 gate)
    __syncwarp();
    int cnt = s_cnt[w];

    int b = bh >> 3, hd = bh & 7;
    float* outp = &g_attn[((size_t)(b * SS + q0 + w)) * DD + hd * DH + lane * 2];

    if (hent >= 1.2f && cnt <= CAP) {
        // rescue: exact fp32 scores for candidates; exact argmax + tie set
        const float* qrow = Q + w * DH;     // fp32 Q row (L2-resident)
        float q_lo = qrow[lane], q_hi = qrow[lane + 32];
        float m_ex = -3.0e38f;
        for (int t = 0; t < cnt; t++) {
            int j = s_idx[w * CAP + t];
            float part = fmaf(q_lo, KT[(size_t)lane * SS + j],
                              q_hi * KT[(size_t)(lane + 32) * SS + j]);
            float s = warpSumF(part) * scale;
            if (lane == 0) s_exv[w * CAP + t] = s;
            m_ex = fmaxf(m_ex, s);
        }
        __syncwarp();
        int tiec = 0;
        float a0 = 0.f, a1 = 0.f;
        int d0 = lane * 2;
        for (int t = 0; t < cnt; t++) {
            if (s_exv[w * CAP + t] == m_ex) {
                tiec++;
                int j = s_idx[w * CAP + t];
                float2 vv = *(const float2*)(V + (size_t)j * DH + d0);
                a0 += vv.x; a1 += vv.y;
            }
        }
        float wgt = 1.0f / ((float)tiec + EPSF * z);
        float2 o; o.x = a0 * wgt; o.y = a1 * wgt;
        *(float2*)outp = o;
    } else {
        // ---- cold exact fallback: full fp32 recompute, reference semantics -
        const float* qrow = Q + w * DH;
        float fb[64];
        for (int jj = 0; jj < 64; jj++) {
            int j = lane + (jj << 5);
            float s = 0.f;
            for (int d = 0; d < DH; d++)
                s = fmaf(qrow[d], KT[(size_t)d * SS + j], s);
            fb[jj] = s * scale;
        }
        float m2 = -3.0e38f;
        for (int jj = 0; jj < 64; jj++) m2 = fmaxf(m2, fb[jj]);
        m2 = warpMaxF(m2);
        float z2 = 0.f;
        for (int jj = 0; jj < 64; jj++) z2 += expf(fb[jj] - m2);
        z2 = warpSumF(z2);
        float invZ = 1.0f / z2;
        float he = 0.f;
        for (int jj = 0; jj < 64; jj++) {
            float p  = expf(fb[jj] - m2);
            float ww = p * invZ;
            he -= ww * logf(ww + EPSF);
        }
        he = warpSumF(he);
        int tk = (int)(32.0f * (1.0f - he));
        tk = tk < 1 ? 1 : (tk > MAXK ? MAXK : tk);

        unsigned thr_u;
        if (tk == 1) {
            thr_u = ordf(m2);
        } else {
            thr_u = 0xFFFFFFFFu;
            int removed = 0;
            while (removed < tk) {
                unsigned best = 0u;
                for (int jj = 0; jj < 64; jj++) {
                    unsigned u = ordf(fb[jj]);
                    if (u < thr_u && u > best) best = u;
                }
                best = warpMaxU(best);
                int c = 0;
                for (int jj = 0; jj < 64; jj++) c += (ordf(fb[jj]) == best);
                c = warpSumI(c);
                removed += c;
                thr_u = best;
            }
        }

        float P = 0.f;
        for (int jj = 0; jj < 64; jj++)
            if (ordf(fb[jj]) >= thr_u) P += expf(fb[jj] - m2);
        P = warpSumF(P);
        float invDen = 1.0f / (P + EPSF * z2);

        float r0 = 0.f, r1 = 0.f;
        for (int dd = 0; dd < DH; dd += 2) {
            float a0 = 0.f, a1 = 0.f;
            for (int jj = 0; jj < 64; jj++) {
                float s = fb[jj];
                if (ordf(s) >= thr_u) {
                    int j = lane + (jj << 5);
                    float p = expf(s - m2);
                    float2 vv = *(const float2*)(V + (size_t)j * DH + dd);
                    a0 = fmaf(p, vv.x, a0);
                    a1 = fmaf(p, vv.y, a1);
                }
            }
            a0 = warpSumF(a0);
            a1 = warpSumF(a1);
            if (lane == (dd >> 1)) { r0 = a0; r1 = a1; }
        }
        float2 o; o.x = r0 * invDen; o.y = r1 * invDen;
        *(float2*)outp = o;
    }
}

// ---------------- launch -----------------------------------------------------
extern "C" void kernel_launch(void* const* d_in, const int* in_sizes, int n_in,
                              void* d_out, int out_size)
{
    const float* x     = (const float*)d_in[0];
    const float* w_in  = (const float*)d_in[1];
    const float* b_in  = (const float*)d_in[2];
    const float* w_out = (const float*)d_in[3];
    const float* b_out = (const float*)d_in[4];
    float* out = (float*)d_out;

    float* pattn = nullptr;
    cudaGetSymbolAddress((void**)&pattn, g_attn);

    cudaFuncSetAttribute(attn_kernel,
                         cudaFuncAttributeMaxDynamicSharedMemorySize, ATTN_SMEM);

    // 1) QKV projection with head-layout scatter (768 blocks of 128x64)
    sgemm_nt<1><<<dim3((3*DD)/64, (BB*SS)/128), 256>>>(
        x, w_in, b_in, nullptr, BB*SS, 3*DD, DD);

    // 2) fused attention: warp-autonomous mma scores, barrier-free phase 1
    attn_kernel<<<dim3(SS/TQ, BH), ATHREADS, ATTN_SMEM>>>();

    // 3) output projection (256 blocks of 128x64)
    sgemm_nt<0><<<dim3(DD/64, (BB*SS)/128), 256>>>(
        pattn, w_out, b_out, out, BB*SS, DD, DD);
}